// round 4
// baseline (speedup 1.0000x reference)
#include <cuda_runtime.h>
#include <math.h>

// ---------------- problem constants ----------------
#define BB 4
#define CC 768
#define FF 256
#define H0 32
#define W0 32
#define N0 (H0*W0)          // 1024

// ---------------- scratch buffers (static __device__, no allocs) ----------------
__device__ float g_x0 [BB*FF*N0];          // fused (B,256,32,32)
__device__ float g_x1 [BB*FF*N0];          // enhanced
__device__ float g_off1[BB*32*N0];         // offsets stage 1
__device__ float g_up1[BB*FF*4*N0];        // (B,256,64,64)
__device__ float g_c1 [BB*FF*4*N0];        // conv1 out
__device__ float g_off2[BB*32*4*N0];       // offsets stage 2
__device__ float g_up2[BB*FF*16*N0];       // (B,256,128,128)
__device__ float g_c2 [BB*FF*16*N0];       // conv2 out

// ---------------- 1. fusion: 4x GEMM (4096x768 @ 768x256) + GELU + weighted sum ----------------
__global__ __launch_bounds__(256) void k_fusion(
    const float* __restrict__ fa, const float* __restrict__ fb,
    const float* __restrict__ fc, const float* __restrict__ fd,
    const float* __restrict__ proj_w, const float* __restrict__ lwp)
{
    __shared__ __align__(16) float As[32][32];
    __shared__ __align__(16) float Bs[32][32];

    const int b   = blockIdx.z;
    const int n0  = blockIdx.x * 32;
    const int fo0 = blockIdx.y * 32;
    const int tx  = threadIdx.x;      // n within tile
    const int ty  = threadIdx.y;      // f quad
    const int tid = ty * 32 + tx;

    // softmax of 4 layer weights (cheap, per-thread, deterministic)
    float w0 = lwp[0], w1 = lwp[1], w2 = lwp[2], w3 = lwp[3];
    float mx = fmaxf(fmaxf(w0, w1), fmaxf(w2, w3));
    float e0 = expf(w0 - mx), e1 = expf(w1 - mx), e2 = expf(w2 - mx), e3 = expf(w3 - mx);
    float inv = 1.0f / (e0 + e1 + e2 + e3);
    float lw[4] = {e0 * inv, e1 * inv, e2 * inv, e3 * inv};

    const float* fs[4] = {fa, fb, fc, fd};

    float outacc[4] = {0.f, 0.f, 0.f, 0.f};

    for (int l = 0; l < 4; l++) {
        float acc[4] = {0.f, 0.f, 0.f, 0.f};
        const float* fin = fs[l] + (size_t)b * CC * N0;
        const float* wpl = proj_w + (size_t)l * CC * FF;
        for (int c0 = 0; c0 < CC; c0 += 32) {
            #pragma unroll
            for (int r = 0; r < 4; r++) {
                int idx = tid + r * 256;
                int c = idx >> 5, n = idx & 31;
                As[c][n] = fin[(c0 + c) * N0 + n0 + n];
                Bs[c][n] = wpl[(c0 + c) * FF + fo0 + n];
            }
            __syncthreads();
            #pragma unroll
            for (int c = 0; c < 32; c++) {
                float a = As[c][tx];
                float4 bv = *(const float4*)&Bs[c][ty * 4];
                acc[0] = fmaf(a, bv.x, acc[0]);
                acc[1] = fmaf(a, bv.y, acc[1]);
                acc[2] = fmaf(a, bv.z, acc[2]);
                acc[3] = fmaf(a, bv.w, acc[3]);
            }
            __syncthreads();
        }
        #pragma unroll
        for (int q = 0; q < 4; q++) {
            float v = acc[q];
            float gelu = 0.5f * v * (1.0f + erff(v * 0.70710678118654752f));
            outacc[q] = fmaf(lw[l], gelu, outacc[q]);
        }
    }
    #pragma unroll
    for (int q = 0; q < 4; q++)
        g_x0[((size_t)b * FF + (fo0 + ty * 4 + q)) * N0 + n0 + tx] = outacc[q];
}

// ---------------- 2. depthwise 3x3 + BN + residual ReLU ----------------
__global__ __launch_bounds__(256) void k_dw(
    const float* __restrict__ dww, const float* __restrict__ bn)
{
    int idx = blockIdx.x * 256 + threadIdx.x;           // B*256*1024 total
    int w = idx & 31, h = (idx >> 5) & 31, f = (idx >> 10) & 255, b = idx >> 18;
    const float* pl = g_x0 + ((size_t)b * FF + f) * N0;
    float acc = 0.f;
    #pragma unroll
    for (int dy = 0; dy < 3; dy++) {
        int yy = h + dy - 1;
        if (yy < 0 || yy >= 32) continue;
        #pragma unroll
        for (int dx = 0; dx < 3; dx++) {
            int xx = w + dx - 1;
            if (xx < 0 || xx >= 32) continue;
            acc = fmaf(pl[yy * 32 + xx], dww[f * 9 + dy * 3 + dx], acc);
        }
    }
    float gm = bn[f], be = bn[256 + f], mn = bn[512 + f], vr = bn[768 + f];
    float bnv = (acc - mn) * gm * rsqrtf(vr + 1e-5f) + be;
    g_x1[idx] = fmaxf(bnv + pl[h * 32 + w], 0.f);
}

// ---------------- 3. offset conv 1x1 (256 -> 32) ----------------
__global__ __launch_bounds__(256) void k_off(
    const float* __restrict__ in, const float* __restrict__ ow,
    const float* __restrict__ ob, float* __restrict__ out, int HW)
{
    int idx = blockIdx.x * 256 + threadIdx.x;
    int hw = idx % HW; int t = idx / HW;
    int k = t & 31; int b = t >> 5;
    float acc = ob[k];
    const float* ib = in + (size_t)b * FF * HW + hw;
    const float* wr = ow + k * FF;
    #pragma unroll 8
    for (int c = 0; c < FF; c++)
        acc = fmaf(ib[(size_t)c * HW], wr[c], acc);
    out[((size_t)b * 32 + k) * HW + hw] = acc;
}

// ---------------- 4. DySample bilinear gather (2x upsample) ----------------
__global__ __launch_bounds__(256) void k_up(
    const float* __restrict__ in, const float* __restrict__ off,
    float* __restrict__ out, int H, int W)
{
    int Ho = 2 * H, Wo = 2 * W;
    int idx = blockIdx.x * 256 + threadIdx.x;
    int X = idx % Wo; int t = idx / Wo;
    int Y = t % Ho;   t /= Ho;
    int cc = t & 255; int b = t >> 8;
    int g = cc >> 6;
    int h = Y >> 1, i = Y & 1, w = X >> 1, j = X & 1;
    int offc = (g << 2) + (i << 1) + j;
    int HW = H * W;
    float ox = off[((size_t)b * 32 + offc) * HW + h * W + w] * 0.25f + (j ? 0.25f : -0.25f);
    float oy = off[((size_t)b * 32 + 16 + offc) * HW + h * W + w] * 0.25f + (i ? 0.25f : -0.25f);
    float px = fminf(fmaxf((float)w + ox, 0.f), (float)(W - 1));
    float py = fminf(fmaxf((float)h + oy, 0.f), (float)(H - 1));
    int x0 = (int)floorf(px), y0 = (int)floorf(py);
    float wx = px - (float)x0, wy = py - (float)y0;
    int x1 = min(x0 + 1, W - 1), y1 = min(y0 + 1, H - 1);
    const float* pl = in + ((size_t)b * FF + cc) * HW;
    float v00 = pl[y0 * W + x0], v01 = pl[y0 * W + x1];
    float v10 = pl[y1 * W + x0], v11 = pl[y1 * W + x1];
    float val = v00 * (1.f - wy) * (1.f - wx) + v01 * (1.f - wy) * wx
              + v10 * wy * (1.f - wx)        + v11 * wy * wx;
    out[(((size_t)b * FF + cc) * Ho + Y) * Wo + X] = val;
}

// ---------------- 5. conv 3x3 (256->256) + BN + ReLU, tiled ----------------
__global__ __launch_bounds__(256) void k_conv3(
    const float* __restrict__ in, const float* __restrict__ wt,
    const float* __restrict__ bn, float* __restrict__ out, int H, int W)
{
    __shared__ float sIn[4][18][18];
    __shared__ __align__(16) float sW[4][9][16];

    const int tx = threadIdx.x, ty = threadIdx.y, tid = ty * 16 + tx;
    const int bz = blockIdx.z;
    const int b = bz >> 4;
    const int fo0 = (bz & 15) << 4;
    const int x0p = blockIdx.x * 16, y0p = blockIdx.y * 16;
    const int gx = x0p + tx, gy = y0p + ty;
    const int HW = H * W;

    float acc[16];
    #pragma unroll
    for (int q = 0; q < 16; q++) acc[q] = 0.f;

    const float* inb = in + (size_t)b * FF * HW;

    for (int cc = 0; cc < FF; cc += 4) {
        // stage input tile 4ci x 18x18 (zero-padded)
        for (int idx = tid; idx < 4 * 324; idx += 256) {
            int ci = idx / 324; int rem = idx - ci * 324;
            int iy = rem / 18, ix = rem - iy * 18;
            int yy = y0p + iy - 1, xx = x0p + ix - 1;
            float v = 0.f;
            if (yy >= 0 && yy < H && xx >= 0 && xx < W)
                v = inb[(size_t)(cc + ci) * HW + yy * W + xx];
            sIn[ci][iy][ix] = v;
        }
        // stage weights [ci][k][fo]
        for (int idx = tid; idx < 576; idx += 256) {
            int fo = idx & 15; int t = idx >> 4;
            int k = t % 9; int ci = t / 9;
            sW[ci][k][fo] = wt[((size_t)(fo0 + fo) * FF + (cc + ci)) * 9 + k];
        }
        __syncthreads();

        #pragma unroll
        for (int ci = 0; ci < 4; ci++) {
            float v[9];
            #pragma unroll
            for (int dy = 0; dy < 3; dy++)
                #pragma unroll
                for (int dx = 0; dx < 3; dx++)
                    v[dy * 3 + dx] = sIn[ci][ty + dy][tx + dx];
            #pragma unroll
            for (int k = 0; k < 9; k++) {
                #pragma unroll
                for (int q = 0; q < 4; q++) {
                    float4 w4 = *(const float4*)&sW[ci][k][q * 4];
                    acc[q * 4 + 0] = fmaf(w4.x, v[k], acc[q * 4 + 0]);
                    acc[q * 4 + 1] = fmaf(w4.y, v[k], acc[q * 4 + 1]);
                    acc[q * 4 + 2] = fmaf(w4.z, v[k], acc[q * 4 + 2]);
                    acc[q * 4 + 3] = fmaf(w4.w, v[k], acc[q * 4 + 3]);
                }
            }
        }
        __syncthreads();
    }

    #pragma unroll
    for (int fo = 0; fo < 16; fo++) {
        int ch = fo0 + fo;
        float gm = bn[ch], be = bn[256 + ch], mn = bn[512 + ch], vr = bn[768 + ch];
        float r = (acc[fo] - mn) * gm * rsqrtf(vr + 1e-5f) + be;
        out[((size_t)b * FF + ch) * HW + gy * W + gx] = fmaxf(r, 0.f);
    }
}

// ---------------- 6. head conv 3x3 (256 -> 1) + bias ----------------
__global__ __launch_bounds__(256) void k_head(
    const float* __restrict__ wt, const float* __restrict__ bias,
    float* __restrict__ out)
{
    __shared__ float sIn[4][18][18];
    __shared__ float sW[4][9];
    const int H = 128, W = 128, HW = H * W;
    const int tx = threadIdx.x, ty = threadIdx.y, tid = ty * 16 + tx;
    const int b = blockIdx.z;
    const int x0p = blockIdx.x * 16, y0p = blockIdx.y * 16;
    const int gx = x0p + tx, gy = y0p + ty;

    const float* inb = g_c2 + (size_t)b * FF * HW;
    float acc = 0.f;

    for (int cc = 0; cc < FF; cc += 4) {
        for (int idx = tid; idx < 4 * 324; idx += 256) {
            int ci = idx / 324; int rem = idx - ci * 324;
            int iy = rem / 18, ix = rem - iy * 18;
            int yy = y0p + iy - 1, xx = x0p + ix - 1;
            float v = 0.f;
            if (yy >= 0 && yy < H && xx >= 0 && xx < W)
                v = inb[(size_t)(cc + ci) * HW + yy * W + xx];
            sIn[ci][iy][ix] = v;
        }
        if (tid < 36) {
            int ci = tid / 9, k = tid % 9;
            sW[ci][k] = wt[(cc + ci) * 9 + k];
        }
        __syncthreads();
        #pragma unroll
        for (int ci = 0; ci < 4; ci++) {
            #pragma unroll
            for (int dy = 0; dy < 3; dy++)
                #pragma unroll
                for (int dx = 0; dx < 3; dx++)
                    acc = fmaf(sIn[ci][ty + dy][tx + dx], sW[ci][dy * 3 + dx], acc);
        }
        __syncthreads();
    }
    out[(size_t)b * HW + gy * W + gx] = acc + bias[0];
}

// ---------------- launch ----------------
extern "C" void kernel_launch(void* const* d_in, const int* in_sizes, int n_in,
                              void* d_out, int out_size)
{
    const float* f1  = (const float*)d_in[0];
    const float* f2  = (const float*)d_in[1];
    const float* f3  = (const float*)d_in[2];
    const float* f4  = (const float*)d_in[3];
    const float* pw  = (const float*)d_in[4];
    const float* lwv = (const float*)d_in[5];
    const float* dww = (const float*)d_in[6];
    const float* bne = (const float*)d_in[7];
    const float* ow1 = (const float*)d_in[8];
    const float* ob1 = (const float*)d_in[9];
    const float* cw1 = (const float*)d_in[10];
    const float* bn1 = (const float*)d_in[11];
    const float* ow2 = (const float*)d_in[12];
    const float* ob2 = (const float*)d_in[13];
    const float* cw2 = (const float*)d_in[14];
    const float* bn2 = (const float*)d_in[15];
    const float* hw  = (const float*)d_in[16];
    const float* hb  = (const float*)d_in[17];
    float* out = (float*)d_out;

    float *p_x1, *p_off1, *p_up1, *p_c1, *p_off2, *p_up2, *p_c2;
    cudaGetSymbolAddress((void**)&p_x1,  g_x1);
    cudaGetSymbolAddress((void**)&p_off1, g_off1);
    cudaGetSymbolAddress((void**)&p_up1, g_up1);
    cudaGetSymbolAddress((void**)&p_c1,  g_c1);
    cudaGetSymbolAddress((void**)&p_off2, g_off2);
    cudaGetSymbolAddress((void**)&p_up2, g_up2);
    cudaGetSymbolAddress((void**)&p_c2,  g_c2);

    // 1. fusion GEMM + gelu + weighted sum -> g_x0 (B,256,32,32)
    k_fusion<<<dim3(N0 / 32, FF / 32, BB), dim3(32, 8)>>>(f1, f2, f3, f4, pw, lwv);
    // 2. depthwise + BN + residual relu -> g_x1
    k_dw<<<(BB * FF * N0) / 256, 256>>>(dww, bne);
    // 3a. offsets stage 1
    k_off<<<(BB * 32 * N0) / 256, 256>>>(p_x1, ow1, ob1, p_off1, N0);
    // 3b. upsample to 64x64
    k_up<<<(BB * FF * 4 * N0) / 256, 256>>>(p_x1, p_off1, p_up1, 32, 32);
    // 3c. conv1 + BN + relu
    k_conv3<<<dim3(4, 4, BB * 16), dim3(16, 16)>>>(p_up1, cw1, bn1, p_c1, 64, 64);
    // 4a. offsets stage 2
    k_off<<<(BB * 32 * 4 * N0) / 256, 256>>>(p_c1, ow2, ob2, p_off2, 4 * N0);
    // 4b. upsample to 128x128
    k_up<<<(BB * FF * 16 * N0) / 256, 256>>>(p_c1, p_off2, p_up2, 64, 64);
    // 4c. conv2 + BN + relu
    k_conv3<<<dim3(8, 8, BB * 16), dim3(16, 16)>>>(p_up2, cw2, bn2, p_c2, 128, 128);
    // 5. head conv
    k_head<<<dim3(8, 8, BB), dim3(16, 16)>>>(hw, hb, out);
}

// round 8
// speedup vs baseline: 2.2253x; 2.2253x over previous
#include <cuda_runtime.h>
#include <cuda_bf16.h>
#include <cstdint>
#include <math.h>

#define BB 4
#define CC 768
#define FF 256
#define N0 1024

// ---------------- scratch ----------------
__device__ float g_x0 [BB*FF*N0];
__device__ float g_x1 [BB*FF*N0];
__device__ float g_off1[BB*32*N0];
__device__ float g_up1[BB*FF*4*N0];
__device__ float g_c1 [BB*FF*4*N0];
__device__ float g_off2[BB*32*4*N0];
__device__ float g_up2[BB*FF*16*N0];
__device__ float g_c2 [BB*FF*16*N0];
__device__ __nv_bfloat162 g_w1hl[9*256*256];   // [kpos][ci][co] {hi,lo}
__device__ __nv_bfloat162 g_w2hl[9*256*256];

// ---------------- helpers ----------------
__device__ __forceinline__ uint32_t smem_u32(const void* p) {
    uint32_t a; asm("{ .reg .u64 t; cvta.to.shared.u64 t, %1; cvt.u32.u64 %0, t; }"
                    : "=r"(a) : "l"(p)); return a;
}
#define SWZ(x) ((uint32_t)(x) ^ ((((uint32_t)(x)) >> 3) & 0x70u))

__device__ __forceinline__ void ldsm_x4(uint32_t (&r)[4], uint32_t addr) {
    asm volatile("ldmatrix.sync.aligned.m8n8.x4.shared.b16 {%0,%1,%2,%3}, [%4];"
        : "=r"(r[0]), "=r"(r[1]), "=r"(r[2]), "=r"(r[3]) : "r"(addr));
}
__device__ __forceinline__ void mma16816(float* d, const uint32_t* a, const uint32_t* b) {
    asm volatile("mma.sync.aligned.m16n8k16.row.col.f32.bf16.bf16.f32 "
        "{%0,%1,%2,%3}, {%4,%5,%6,%7}, {%8,%9}, {%0,%1,%2,%3};"
        : "+f"(d[0]), "+f"(d[1]), "+f"(d[2]), "+f"(d[3])
        : "r"(a[0]), "r"(a[1]), "r"(a[2]), "r"(a[3]), "r"(b[0]), "r"(b[1]));
}

// ---------------- weight pre-split: OIHW -> [kpos][ci][co]{hi,lo} ----------------
__global__ __launch_bounds__(256) void k_prep_w(const float* __restrict__ w1,
                                                const float* __restrict__ w2) {
    int idx = blockIdx.x * 256 + threadIdx.x;        // 2*589824
    int which = idx >= 589824;
    int t = which ? idx - 589824 : idx;
    int kpos = t >> 16, ci = (t >> 8) & 255, co = t & 255;
    float v = (which ? w2 : w1)[(co * 256 + ci) * 9 + kpos];
    __nv_bfloat16 h = __float2bfloat16(v);
    __nv_bfloat16 l = __float2bfloat16(v - __bfloat162float(h));
    (which ? g_w2hl : g_w1hl)[t] = __halves2bfloat162(h, l);
}

// ---------------- fusion GEMM (fp32, known-good) ----------------
__global__ __launch_bounds__(256) void k_fusion(
    const float* __restrict__ fa, const float* __restrict__ fb,
    const float* __restrict__ fc, const float* __restrict__ fd,
    const float* __restrict__ proj_w, const float* __restrict__ lwp)
{
    __shared__ __align__(16) float As[32][32];
    __shared__ __align__(16) float Bs[32][32];
    const int b = blockIdx.z, n0 = blockIdx.x * 32, fo0 = blockIdx.y * 32;
    const int tx = threadIdx.x, ty = threadIdx.y, tid = ty * 32 + tx;
    float w0 = lwp[0], w1 = lwp[1], w2 = lwp[2], w3 = lwp[3];
    float mx = fmaxf(fmaxf(w0, w1), fmaxf(w2, w3));
    float e0 = expf(w0-mx), e1 = expf(w1-mx), e2 = expf(w2-mx), e3 = expf(w3-mx);
    float inv = 1.0f / (e0+e1+e2+e3);
    float lw[4] = {e0*inv, e1*inv, e2*inv, e3*inv};
    const float* fs[4] = {fa, fb, fc, fd};
    float outacc[4] = {0.f,0.f,0.f,0.f};
    for (int l = 0; l < 4; l++) {
        float acc[4] = {0.f,0.f,0.f,0.f};
        const float* fin = fs[l] + (size_t)b * CC * N0;
        const float* wpl = proj_w + (size_t)l * CC * FF;
        for (int c0 = 0; c0 < CC; c0 += 32) {
            #pragma unroll
            for (int r = 0; r < 4; r++) {
                int idx = tid + r * 256, c = idx >> 5, n = idx & 31;
                As[c][n] = fin[(c0+c)*N0 + n0 + n];
                Bs[c][n] = wpl[(c0+c)*FF + fo0 + n];
            }
            __syncthreads();
            #pragma unroll
            for (int c = 0; c < 32; c++) {
                float a = As[c][tx];
                float4 bv = *(const float4*)&Bs[c][ty*4];
                acc[0]=fmaf(a,bv.x,acc[0]); acc[1]=fmaf(a,bv.y,acc[1]);
                acc[2]=fmaf(a,bv.z,acc[2]); acc[3]=fmaf(a,bv.w,acc[3]);
            }
            __syncthreads();
        }
        #pragma unroll
        for (int q = 0; q < 4; q++) {
            float v = acc[q];
            outacc[q] = fmaf(lw[l], 0.5f*v*(1.0f+erff(v*0.70710678118654752f)), outacc[q]);
        }
    }
    #pragma unroll
    for (int q = 0; q < 4; q++)
        g_x0[((size_t)b*FF + fo0 + ty*4 + q)*N0 + n0 + tx] = outacc[q];
}

// ---------------- depthwise + BN + residual ----------------
__global__ __launch_bounds__(256) void k_dw(const float* __restrict__ dww,
                                            const float* __restrict__ bn) {
    int idx = blockIdx.x * 256 + threadIdx.x;
    int w = idx & 31, h = (idx >> 5) & 31, f = (idx >> 10) & 255, b = idx >> 18;
    const float* pl = g_x0 + ((size_t)b*FF + f) * N0;
    float acc = 0.f;
    #pragma unroll
    for (int dy = 0; dy < 3; dy++) {
        int yy = h + dy - 1; if (yy < 0 || yy >= 32) continue;
        #pragma unroll
        for (int dx = 0; dx < 3; dx++) {
            int xx = w + dx - 1; if (xx < 0 || xx >= 32) continue;
            acc = fmaf(pl[yy*32+xx], dww[f*9+dy*3+dx], acc);
        }
    }
    float bnv = (acc - bn[512+f]) * bn[f] * rsqrtf(bn[768+f] + 1e-5f) + bn[256+f];
    g_x1[idx] = fmaxf(bnv + pl[h*32+w], 0.f);
}

// ---------------- offset conv 1x1 (256->32), 32 acc/thread ----------------
__global__ __launch_bounds__(128) void k_off(const float* __restrict__ in,
    const float* __restrict__ ow, const float* __restrict__ ob,
    float* __restrict__ out, int HW) {
    __shared__ __align__(16) float swT[256][32];
    int tid = threadIdx.x;
    for (int idx = tid; idx < 8192; idx += 128)
        swT[idx & 255][idx >> 8] = ow[(idx >> 8) * 256 + (idx & 255)];
    __syncthreads();
    int hw = blockIdx.x * 128 + tid, b = blockIdx.y;
    float acc[32];
    #pragma unroll
    for (int k = 0; k < 32; k++) acc[k] = 0.f;
    const float* ip = in + (size_t)b * FF * HW + hw;
    for (int c = 0; c < 256; c++) {
        float v = ip[(size_t)c * HW];
        #pragma unroll
        for (int k8 = 0; k8 < 8; k8++) {
            float4 w4 = *(const float4*)&swT[c][k8*4];
            acc[k8*4+0]=fmaf(v,w4.x,acc[k8*4+0]); acc[k8*4+1]=fmaf(v,w4.y,acc[k8*4+1]);
            acc[k8*4+2]=fmaf(v,w4.z,acc[k8*4+2]); acc[k8*4+3]=fmaf(v,w4.w,acc[k8*4+3]);
        }
    }
    #pragma unroll
    for (int k = 0; k < 32; k++)
        out[((size_t)b*32 + k)*HW + hw] = acc[k] + ob[k];
}

// ---------------- DySample bilinear 2x ----------------
__global__ __launch_bounds__(256) void k_up(const float* __restrict__ in,
    const float* __restrict__ off, float* __restrict__ out, int H, int W) {
    int Ho = 2*H, Wo = 2*W;
    int idx = blockIdx.x * 256 + threadIdx.x;
    int X = idx % Wo; int t = idx / Wo;
    int Y = t % Ho;   t /= Ho;
    int cc = t & 255, b = t >> 8, g = cc >> 6;
    int h = Y >> 1, i = Y & 1, w = X >> 1, j = X & 1;
    int offc = (g << 2) + (i << 1) + j, HW = H * W;
    float ox = off[((size_t)b*32 + offc)*HW + h*W + w] * 0.25f + (j ? 0.25f : -0.25f);
    float oy = off[((size_t)b*32 + 16 + offc)*HW + h*W + w] * 0.25f + (i ? 0.25f : -0.25f);
    float px = fminf(fmaxf((float)w + ox, 0.f), (float)(W-1));
    float py = fminf(fmaxf((float)h + oy, 0.f), (float)(H-1));
    int x0 = (int)floorf(px), y0 = (int)floorf(py);
    float wx = px - x0, wy = py - y0;
    int x1 = min(x0+1, W-1), y1 = min(y0+1, H-1);
    const float* pl = in + ((size_t)b*FF + cc)*HW;
    float v00=pl[y0*W+x0], v01=pl[y0*W+x1], v10=pl[y1*W+x0], v11=pl[y1*W+x1];
    out[(((size_t)b*FF + cc)*Ho + Y)*Wo + X] =
        v00*(1.f-wy)*(1.f-wx) + v01*(1.f-wy)*wx + v10*wy*(1.f-wx) + v11*wy*wx;
}

// ---------------- HMMA implicit-GEMM conv 3x3 256->256 + BN + ReLU ----------------
// smem (1024-aligned base): sSc@0 sSh@1024 Ah@2048(16K) Al@18432(16K)
//                            Bh@34816(32K) Bl@67584(32K)  end=99328
#define CM_SMEM (99328 + 1024)
__global__ __launch_bounds__(512) void k_conv_mma(
    const float* __restrict__ in, const __nv_bfloat162* __restrict__ whl,
    const float* __restrict__ bn, float* __restrict__ out, int W, int logW)
{
    extern __shared__ char smem_raw[];
    const uint32_t sb0 = smem_u32(smem_raw);
    const uint32_t sa = (sb0 + 1023u) & ~1023u;
    char* smem = smem_raw + (sa - sb0);
    const int tid = threadIdx.x, wid = tid >> 5, lane = tid & 31;
    const int HW = W * W;
    const int b = blockIdx.y;
    const int p0 = blockIdx.x * 128;

    float* sSc = (float*)(smem);
    float* sSh = (float*)(smem + 1024);
    if (tid < 256) {
        float sc = bn[tid] * rsqrtf(bn[768 + tid] + 1e-5f);
        sSc[tid] = sc;
        sSh[tid] = bn[256 + tid] - bn[512 + tid] * sc;
    }

    char* Ah = smem + 2048;  char* Al = smem + 18432;
    char* Bh = smem + 34816; char* Bl = smem + 67584;
    const uint32_t aAh = sa + 2048, aAl = sa + 18432;
    const uint32_t aBh = sa + 34816, aBl = sa + 67584;

    // warp tile: M 32 x N 64;  warp grid 4(M) x 4(N)
    const int m0 = (wid & 3) * 32;
    const int n0 = (wid >> 2) * 64;
    // ldmatrix per-lane addressing offsets
    const int aRow = lane & 15, aCol = (lane >> 4) * 8;           // A x4
    const int bRow = (lane & 7) + ((lane >> 4) << 3);             // B x4
    const int bCol = ((lane >> 3) & 1) * 8;

    float acc[2][8][4];
    #pragma unroll
    for (int i = 0; i < 2; i++)
        #pragma unroll
        for (int j = 0; j < 8; j++)
            #pragma unroll
            for (int q = 0; q < 4; q++) acc[i][j][q] = 0.f;

    for (int ch = 0; ch < 36; ch++) {
        const int kpos = ch >> 2;
        const int ci0 = (ch & 3) * 64;
        const int ky = kpos / 3 - 1, kx = kpos % 3 - 1;
        __syncthreads();     // previous chunk's mma reads complete
        // ---- fill A: 128 px x 64 ci (pairs), hi/lo split ----
        for (int idx = tid; idx < 128 * 32; idx += 512) {
            int m = idx & 127, c2 = idx >> 7;
            int pix = p0 + m;
            int y = (pix >> logW) + ky, x = (pix & (W - 1)) + kx;
            bool ok = (y >= 0 && y < W && x >= 0 && x < W);
            const float* ip = in + ((size_t)b * FF + ci0 + 2 * c2) * HW + y * W + x;
            float a0 = ok ? ip[0]  : 0.f;
            float a1 = ok ? ip[HW] : 0.f;
            __nv_bfloat16 h0 = __float2bfloat16(a0), h1 = __float2bfloat16(a1);
            __nv_bfloat16 l0 = __float2bfloat16(a0 - __bfloat162float(h0));
            __nv_bfloat16 l1 = __float2bfloat16(a1 - __bfloat162float(h1));
            uint32_t sw = SWZ(m * 128 + c2 * 4);
            *(__nv_bfloat162*)(Ah + sw) = __halves2bfloat162(h0, h1);
            *(__nv_bfloat162*)(Al + sw) = __halves2bfloat162(l0, l1);
        }
        // ---- fill B: 256 co x 64 ci (pairs), from pre-split weights ----
        for (int idx = tid; idx < 256 * 32; idx += 512) {
            int co = idx & 255, c2 = idx >> 8;
            const __nv_bfloat162* wp = whl + ((size_t)kpos * 256 + ci0 + 2 * c2) * 256 + co;
            __nv_bfloat162 wa = wp[0], wb = wp[256];
            uint32_t sw = SWZ(co * 128 + c2 * 4);
            *(__nv_bfloat162*)(Bh + sw) = __halves2bfloat162(wa.x, wb.x);
            *(__nv_bfloat162*)(Bl + sw) = __halves2bfloat162(wa.y, wb.y);
        }
        __syncthreads();
        // ---- 4 k16-steps of mma ----
        #pragma unroll
        for (int ks = 0; ks < 4; ks++) {
            const int k0 = ks * 16;
            uint32_t ah[2][4], al[2][4], bh[4][4], bl[4][4];
            #pragma unroll
            for (int mf = 0; mf < 2; mf++) {
                uint32_t off = SWZ((m0 + mf * 16 + aRow) * 128 + (k0 + aCol) * 2);
                ldsm_x4(ah[mf], aAh + off);
                ldsm_x4(al[mf], aAl + off);
            }
            #pragma unroll
            for (int nb = 0; nb < 4; nb++) {
                uint32_t off = SWZ((n0 + nb * 16 + bRow) * 128 + (k0 + bCol) * 2);
                ldsm_x4(bh[nb], aBh + off);
                ldsm_x4(bl[nb], aBl + off);
            }
            #pragma unroll
            for (int mf = 0; mf < 2; mf++)
                #pragma unroll
                for (int nb = 0; nb < 4; nb++)
                    #pragma unroll
                    for (int oc = 0; oc < 2; oc++) {
                        float* d = acc[mf][nb * 2 + oc];
                        mma16816(d, ah[mf], &bh[nb][oc * 2]);
                        mma16816(d, ah[mf], &bl[nb][oc * 2]);
                        mma16816(d, al[mf], &bh[nb][oc * 2]);
                    }
        }
    }

    // ---- epilogue: BN + ReLU, scatter to NCHW ----
    const int group = lane >> 2, tig = lane & 3;
    #pragma unroll
    for (int mf = 0; mf < 2; mf++)
        #pragma unroll
        for (int nb = 0; nb < 4; nb++)
            #pragma unroll
            for (int oc = 0; oc < 2; oc++) {
                const float* d = acc[mf][nb * 2 + oc];
                int co = n0 + nb * 16 + oc * 8 + tig * 2;
                int m  = m0 + mf * 16 + group;
                float s0 = sSc[co], h0 = sSh[co], s1 = sSc[co+1], h1 = sSh[co+1];
                size_t o0 = ((size_t)b * FF + co) * HW + p0 + m;
                out[o0]           = fmaxf(fmaf(d[0], s0, h0), 0.f);
                out[o0 + HW]      = fmaxf(fmaf(d[1], s1, h1), 0.f);
                out[o0 + 8]       = fmaxf(fmaf(d[2], s0, h0), 0.f);
                out[o0 + HW + 8]  = fmaxf(fmaf(d[3], s1, h1), 0.f);
            }
}

// ---------------- head conv 3x3 (256->1) ----------------
__global__ __launch_bounds__(256) void k_head(const float* __restrict__ wt,
    const float* __restrict__ bias, float* __restrict__ out) {
    __shared__ float sIn[4][18][18];
    __shared__ float sW[4][9];
    const int H = 128, W = 128, HW = H * W;
    const int tx = threadIdx.x, ty = threadIdx.y, tid = ty * 16 + tx;
    const int b = blockIdx.z, x0p = blockIdx.x * 16, y0p = blockIdx.y * 16;
    const float* inb = g_c2 + (size_t)b * FF * HW;
    float acc = 0.f;
    for (int cc = 0; cc < FF; cc += 4) {
        for (int idx = tid; idx < 4 * 324; idx += 256) {
            int ci = idx / 324, rem = idx - ci * 324;
            int iy = rem / 18, ix = rem - iy * 18;
            int yy = y0p + iy - 1, xx = x0p + ix - 1;
            float v = 0.f;
            if (yy >= 0 && yy < H && xx >= 0 && xx < W)
                v = inb[(size_t)(cc + ci) * HW + yy * W + xx];
            sIn[ci][iy][ix] = v;
        }
        if (tid < 36) sW[tid / 9][tid % 9] = wt[(cc + tid / 9) * 9 + tid % 9];
        __syncthreads();
        #pragma unroll
        for (int ci = 0; ci < 4; ci++)
            #pragma unroll
            for (int dy = 0; dy < 3; dy++)
                #pragma unroll
                for (int dx = 0; dx < 3; dx++)
                    acc = fmaf(sIn[ci][ty+dy][tx+dx], sW[ci][dy*3+dx], acc);
        __syncthreads();
    }
    out[(size_t)b * HW + (y0p + ty) * W + (x0p + tx)] = acc + bias[0];
}

// ---------------- launch ----------------
extern "C" void kernel_launch(void* const* d_in, const int* in_sizes, int n_in,
                              void* d_out, int out_size)
{
    const float* f1  = (const float*)d_in[0];
    const float* f2  = (const float*)d_in[1];
    const float* f3  = (const float*)d_in[2];
    const float* f4  = (const float*)d_in[3];
    const float* pw  = (const float*)d_in[4];
    const float* lwv = (const float*)d_in[5];
    const float* dww = (const float*)d_in[6];
    const float* bne = (const float*)d_in[7];
    const float* ow1 = (const float*)d_in[8];
    const float* ob1 = (const float*)d_in[9];
    const float* cw1 = (const float*)d_in[10];
    const float* bn1 = (const float*)d_in[11];
    const float* ow2 = (const float*)d_in[12];
    const float* ob2 = (const float*)d_in[13];
    const float* cw2 = (const float*)d_in[14];
    const float* bn2 = (const float*)d_in[15];
    const float* hw  = (const float*)d_in[16];
    const float* hb  = (const float*)d_in[17];
    float* out = (float*)d_out;

    float *p_x1, *p_off1, *p_up1, *p_c1, *p_off2, *p_up2, *p_c2;
    __nv_bfloat162 *p_w1, *p_w2;
    cudaGetSymbolAddress((void**)&p_x1,  g_x1);
    cudaGetSymbolAddress((void**)&p_off1, g_off1);
    cudaGetSymbolAddress((void**)&p_up1, g_up1);
    cudaGetSymbolAddress((void**)&p_c1,  g_c1);
    cudaGetSymbolAddress((void**)&p_off2, g_off2);
    cudaGetSymbolAddress((void**)&p_up2, g_up2);
    cudaGetSymbolAddress((void**)&p_c2,  g_c2);
    cudaGetSymbolAddress((void**)&p_w1,  g_w1hl);
    cudaGetSymbolAddress((void**)&p_w2,  g_w2hl);

    cudaFuncSetAttribute(k_conv_mma, cudaFuncAttributeMaxDynamicSharedMemorySize, CM_SMEM);

    k_prep_w<<<(2*589824)/256, 256>>>(cw1, cw2);
    k_fusion<<<dim3(N0/32, FF/32, BB), dim3(32, 8)>>>(f1, f2, f3, f4, pw, lwv);
    k_dw<<<(BB*FF*N0)/256, 256>>>(dww, bne);
    k_off<<<dim3(N0/128, BB), 128>>>(p_x1, ow1, ob1, p_off1, N0);
    k_up<<<(BB*FF*4*N0)/256, 256>>>(p_x1, p_off1, p_up1, 32, 32);
    k_conv_mma<<<dim3(4*N0/128, BB), 512, CM_SMEM>>>(p_up1, p_w1, bn1, p_c1, 64, 6);
    k_off<<<dim3(4*N0/128, BB), 128>>>(p_c1, ow2, ob2, p_off2, 4*N0);
    k_up<<<(BB*FF*16*N0)/256, 256>>>(p_c1, p_off2, p_up2, 64, 64);
    k_conv_mma<<<dim3(16*N0/128, BB), 512, CM_SMEM>>>(p_up2, p_w2, bn2, p_c2, 128, 7);
    k_head<<<dim3(8, 8, BB), dim3(16, 16)>>>(hw, hb, out);
}

// round 9
// speedup vs baseline: 2.3950x; 1.0762x over previous
#include <cuda_runtime.h>
#include <cuda_bf16.h>
#include <cstdint>
#include <math.h>

#define BB 4
#define CC 768
#define FF 256
#define N0 1024

// ---------------- scratch ----------------
__device__ float g_x0 [BB*FF*N0];
__device__ float g_x1 [BB*FF*N0];
__device__ float g_off1[BB*32*N0];
__device__ float g_up1[BB*FF*4*N0];
__device__ float g_c1 [BB*FF*4*N0];
__device__ float g_off2[BB*32*4*N0];
__device__ float g_up2[BB*FF*16*N0];
__device__ float g_c2 [BB*FF*16*N0];
__device__ __nv_bfloat162 g_w1hl[9*256*256];   // [kpos][ci][co] {hi,lo}
__device__ __nv_bfloat162 g_w2hl[9*256*256];

// ---------------- helpers ----------------
__device__ __forceinline__ uint32_t smem_u32(const void* p) {
    uint32_t a; asm("{ .reg .u64 t; cvta.to.shared.u64 t, %1; cvt.u32.u64 %0, t; }"
                    : "=r"(a) : "l"(p)); return a;
}
#define SWZ(x) ((uint32_t)(x) ^ ((((uint32_t)(x)) >> 3) & 0x70u))

__device__ __forceinline__ void ldsm_x4(uint32_t (&r)[4], uint32_t addr) {
    asm volatile("ldmatrix.sync.aligned.m8n8.x4.shared.b16 {%0,%1,%2,%3}, [%4];"
        : "=r"(r[0]), "=r"(r[1]), "=r"(r[2]), "=r"(r[3]) : "r"(addr));
}
__device__ __forceinline__ void mma16816(float* d, const uint32_t* a, const uint32_t* b) {
    asm volatile("mma.sync.aligned.m16n8k16.row.col.f32.bf16.bf16.f32 "
        "{%0,%1,%2,%3}, {%4,%5,%6,%7}, {%8,%9}, {%0,%1,%2,%3};"
        : "+f"(d[0]), "+f"(d[1]), "+f"(d[2]), "+f"(d[3])
        : "r"(a[0]), "r"(a[1]), "r"(a[2]), "r"(a[3]), "r"(b[0]), "r"(b[1]));
}
__device__ __forceinline__ void split_bf16(float v, __nv_bfloat16& h, __nv_bfloat16& l) {
    h = __float2bfloat16(v);
    l = __float2bfloat16(v - __bfloat162float(h));
}

// ---------------- weight pre-split: OIHW -> [kpos][ci][co]{hi,lo} ----------------
__global__ __launch_bounds__(256) void k_prep_w(const float* __restrict__ w1,
                                                const float* __restrict__ w2) {
    int idx = blockIdx.x * 256 + threadIdx.x;        // 2*589824
    int which = idx >= 589824;
    int t = which ? idx - 589824 : idx;
    int kpos = t >> 16, ci = (t >> 8) & 255, co = t & 255;
    float v = (which ? w2 : w1)[(co * 256 + ci) * 9 + kpos];
    __nv_bfloat16 h, l; split_bf16(v, h, l);
    (which ? g_w2hl : g_w1hl)[t] = __halves2bfloat162(h, l);
}

// ---------------- fusion GEMM: HMMA bf16 3-term, GELU + weighted layer sum ----------------
// smem (1024-aligned): Ah@0(8K) Al@8192(8K) Bh@16384(16K) Bl@32768(16K) end=49152
#define FM_SMEM (49152 + 1024)
__global__ __launch_bounds__(256) void k_fusion_mma(
    const float* __restrict__ fa, const float* __restrict__ fb,
    const float* __restrict__ fc, const float* __restrict__ fd,
    const float* __restrict__ proj_w, const float* __restrict__ lwp)
{
    extern __shared__ char smem_raw[];
    const uint32_t sb0 = smem_u32(smem_raw);
    const uint32_t sa = (sb0 + 1023u) & ~1023u;
    char* smem = smem_raw + (sa - sb0);
    const int tid = threadIdx.x, wid = tid >> 5, lane = tid & 31;
    const int mt0 = blockIdx.x * 64;       // 64 tokens per CTA
    const int f0  = blockIdx.y * 128;      // 128 out-features per CTA
    const int m0 = (wid & 1) * 32;         // warp tile 32x32, warp grid 2(M) x 4(N)
    const int n0 = (wid >> 1) * 32;

    char* Ah = smem;          char* Al = smem + 8192;
    char* Bh = smem + 16384;  char* Bl = smem + 32768;
    const uint32_t aAh = sa, aAl = sa + 8192, aBh = sa + 16384, aBl = sa + 32768;

    float w0 = lwp[0], w1 = lwp[1], w2 = lwp[2], w3 = lwp[3];
    float mx = fmaxf(fmaxf(w0, w1), fmaxf(w2, w3));
    float e0 = expf(w0-mx), e1 = expf(w1-mx), e2 = expf(w2-mx), e3 = expf(w3-mx);
    float inv = 1.0f / (e0+e1+e2+e3);
    float lw[4] = {e0*inv, e1*inv, e2*inv, e3*inv};
    const float* fs[4] = {fa, fb, fc, fd};

    const int aRow = lane & 15, aCol = (lane >> 4) * 8;
    const int bRow = (lane & 7) + ((lane >> 4) << 3);
    const int bCol = ((lane >> 3) & 1) * 8;

    float acc[2][4][4], oacc[2][4][4];
    #pragma unroll
    for (int i = 0; i < 2; i++)
        #pragma unroll
        for (int j = 0; j < 4; j++)
            #pragma unroll
            for (int q = 0; q < 4; q++) { acc[i][j][q] = 0.f; oacc[i][j][q] = 0.f; }

    for (int l = 0; l < 4; l++) {
        const float* fl = fs[l];
        for (int ch = 0; ch < 12; ch++) {
            const int kc0 = ch * 64;
            __syncthreads();
            // A: 64 tokens x 64 k (pairs): token m -> f[b][c][n]
            for (int idx = tid; idx < 64 * 32; idx += 256) {
                int m = idx & 63, c2 = idx >> 6;
                int pix = mt0 + m, b = pix >> 10, n = pix & 1023;
                const float* ip = fl + ((size_t)b * CC + kc0 + 2 * c2) * N0 + n;
                float a0 = ip[0], a1 = ip[N0];
                __nv_bfloat16 h0, l0, h1, l1;
                split_bf16(a0, h0, l0); split_bf16(a1, h1, l1);
                uint32_t sw = SWZ(m * 128 + c2 * 4);
                *(__nv_bfloat162*)(Ah + sw) = __halves2bfloat162(h0, h1);
                *(__nv_bfloat162*)(Al + sw) = __halves2bfloat162(l0, l1);
            }
            // B: 128 co x 64 k (pairs): proj_w[l][c][f]
            for (int idx = tid; idx < 128 * 32; idx += 256) {
                int co = idx & 127, c2 = idx >> 7;
                const float* wp = proj_w + ((size_t)l * CC + kc0 + 2 * c2) * FF + f0 + co;
                float b0 = wp[0], b1 = wp[FF];
                __nv_bfloat16 h0, l0, h1, l1;
                split_bf16(b0, h0, l0); split_bf16(b1, h1, l1);
                uint32_t sw = SWZ(co * 128 + c2 * 4);
                *(__nv_bfloat162*)(Bh + sw) = __halves2bfloat162(h0, h1);
                *(__nv_bfloat162*)(Bl + sw) = __halves2bfloat162(l0, l1);
            }
            __syncthreads();
            #pragma unroll
            for (int ks = 0; ks < 4; ks++) {
                const int k0 = ks * 16;
                uint32_t ah[2][4], al[2][4], bh[2][4], bl[2][4];
                #pragma unroll
                for (int mf = 0; mf < 2; mf++) {
                    uint32_t off = SWZ((m0 + mf * 16 + aRow) * 128 + (k0 + aCol) * 2);
                    ldsm_x4(ah[mf], aAh + off);
                    ldsm_x4(al[mf], aAl + off);
                }
                #pragma unroll
                for (int nb = 0; nb < 2; nb++) {
                    uint32_t off = SWZ((n0 + nb * 16 + bRow) * 128 + (k0 + bCol) * 2);
                    ldsm_x4(bh[nb], aBh + off);
                    ldsm_x4(bl[nb], aBl + off);
                }
                #pragma unroll
                for (int mf = 0; mf < 2; mf++)
                    #pragma unroll
                    for (int nb = 0; nb < 2; nb++)
                        #pragma unroll
                        for (int oc = 0; oc < 2; oc++) {
                            float* d = acc[mf][nb * 2 + oc];
                            mma16816(d, ah[mf], &bh[nb][oc * 2]);
                            mma16816(d, ah[mf], &bl[nb][oc * 2]);
                            mma16816(d, al[mf], &bh[nb][oc * 2]);
                        }
            }
        }
        // layer done: GELU + weighted accumulate (registers only)
        #pragma unroll
        for (int i = 0; i < 2; i++)
            #pragma unroll
            for (int j = 0; j < 4; j++)
                #pragma unroll
                for (int q = 0; q < 4; q++) {
                    float v = acc[i][j][q];
                    acc[i][j][q] = 0.f;
                    float g = 0.5f * v * (1.0f + erff(v * 0.70710678118654752f));
                    oacc[i][j][q] = fmaf(lw[l], g, oacc[i][j][q]);
                }
    }
    // epilogue
    const int group = lane >> 2, tig = lane & 3;
    #pragma unroll
    for (int mf = 0; mf < 2; mf++)
        #pragma unroll
        for (int nb = 0; nb < 2; nb++)
            #pragma unroll
            for (int oc = 0; oc < 2; oc++) {
                const float* d = oacc[mf][nb * 2 + oc];
                int co = f0 + n0 + nb * 16 + oc * 8 + tig * 2;
                int m  = mt0 + m0 + mf * 16 + group;
                int b = m >> 10, n = m & 1023;
                size_t o0 = ((size_t)b * FF + co) * N0 + n;
                g_x0[o0]          = d[0];
                g_x0[o0 + N0]     = d[1];
                g_x0[o0 + 8]      = d[2];
                g_x0[o0 + N0 + 8] = d[3];
            }
}

// ---------------- depthwise + BN + residual ----------------
__global__ __launch_bounds__(256) void k_dw(const float* __restrict__ dww,
                                            const float* __restrict__ bn) {
    int idx = blockIdx.x * 256 + threadIdx.x;
    int w = idx & 31, h = (idx >> 5) & 31, f = (idx >> 10) & 255, b = idx >> 18;
    const float* pl = g_x0 + ((size_t)b*FF + f) * N0;
    float acc = 0.f;
    #pragma unroll
    for (int dy = 0; dy < 3; dy++) {
        int yy = h + dy - 1; if (yy < 0 || yy >= 32) continue;
        #pragma unroll
        for (int dx = 0; dx < 3; dx++) {
            int xx = w + dx - 1; if (xx < 0 || xx >= 32) continue;
            acc = fmaf(pl[yy*32+xx], dww[f*9+dy*3+dx], acc);
        }
    }
    float bnv = (acc - bn[512+f]) * bn[f] * rsqrtf(bn[768+f] + 1e-5f) + bn[256+f];
    g_x1[idx] = fmaxf(bnv + pl[h*32+w], 0.f);
}

// ---------------- offset conv 1x1 (256->32): 64px x 4 k-split groups ----------------
// dyn smem: wT[256][32] (32KB) + sred[4][64][33] (33.8KB) = 66560 B
#define KO_SMEM (32768 + 33792)
__global__ __launch_bounds__(256) void k_off(const float* __restrict__ in,
    const float* __restrict__ ow, const float* __restrict__ ob,
    float* __restrict__ out, int HW) {
    extern __shared__ float ko[];
    float (*wT)[32] = (float(*)[32])ko;
    float (*sred)[64][33] = (float(*)[64][33])(ko + 8192);
    const int tid = threadIdx.x;
    for (int idx = tid; idx < 8192; idx += 256)
        wT[idx & 255][idx >> 8] = ow[(idx >> 8) * 256 + (idx & 255)];
    __syncthreads();
    const int px = tid & 63, grp = tid >> 6;
    const int hw = blockIdx.x * 64 + px, b = blockIdx.y;
    float acc[32];
    #pragma unroll
    for (int k = 0; k < 32; k++) acc[k] = 0.f;
    const float* ip = in + ((size_t)b * FF + grp * 64) * HW + hw;
    #pragma unroll 4
    for (int c = 0; c < 64; c++) {
        float v = ip[(size_t)c * HW];
        const float* wr = wT[grp * 64 + c];
        #pragma unroll
        for (int k8 = 0; k8 < 8; k8++) {
            float4 w4 = *(const float4*)&wr[k8 * 4];
            acc[k8*4+0]=fmaf(v,w4.x,acc[k8*4+0]); acc[k8*4+1]=fmaf(v,w4.y,acc[k8*4+1]);
            acc[k8*4+2]=fmaf(v,w4.z,acc[k8*4+2]); acc[k8*4+3]=fmaf(v,w4.w,acc[k8*4+3]);
        }
    }
    #pragma unroll
    for (int k = 0; k < 32; k++) sred[grp][px][k] = acc[k];
    __syncthreads();
    for (int idx = tid; idx < 2048; idx += 256) {
        int k = idx & 31, p = idx >> 5;
        float s = sred[0][p][k] + sred[1][p][k] + sred[2][p][k] + sred[3][p][k] + ob[k];
        out[((size_t)b * 32 + k) * HW + blockIdx.x * 64 + p] = s;
    }
}

// ---------------- DySample bilinear 2x ----------------
__global__ __launch_bounds__(256) void k_up(const float* __restrict__ in,
    const float* __restrict__ off, float* __restrict__ out, int H, int W) {
    int Ho = 2*H, Wo = 2*W;
    int idx = blockIdx.x * 256 + threadIdx.x;
    int X = idx % Wo; int t = idx / Wo;
    int Y = t % Ho;   t /= Ho;
    int cc = t & 255, b = t >> 8, g = cc >> 6;
    int h = Y >> 1, i = Y & 1, w = X >> 1, j = X & 1;
    int offc = (g << 2) + (i << 1) + j, HW = H * W;
    float ox = off[((size_t)b*32 + offc)*HW + h*W + w] * 0.25f + (j ? 0.25f : -0.25f);
    float oy = off[((size_t)b*32 + 16 + offc)*HW + h*W + w] * 0.25f + (i ? 0.25f : -0.25f);
    float px = fminf(fmaxf((float)w + ox, 0.f), (float)(W-1));
    float py = fminf(fmaxf((float)h + oy, 0.f), (float)(H-1));
    int x0 = (int)floorf(px), y0 = (int)floorf(py);
    float wx = px - x0, wy = py - y0;
    int x1 = min(x0+1, W-1), y1 = min(y0+1, H-1);
    const float* pl = in + ((size_t)b*FF + cc)*HW;
    float v00=pl[y0*W+x0], v01=pl[y0*W+x1], v10=pl[y1*W+x0], v11=pl[y1*W+x1];
    out[(((size_t)b*FF + cc)*Ho + Y)*Wo + X] =
        v00*(1.f-wy)*(1.f-wx) + v01*(1.f-wy)*wx + v10*wy*(1.f-wx) + v11*wy*wx;
}

// ---------------- HMMA implicit-GEMM conv 3x3 256->256 + BN + ReLU ----------------
// smem (1024-aligned base): sSc@0 sSh@1024 Ah@2048(16K) Al@18432(16K)
//                            Bh@34816(32K) Bl@67584(32K)  end=99328
#define CM_SMEM (99328 + 1024)
__global__ __launch_bounds__(512) void k_conv_mma(
    const float* __restrict__ in, const __nv_bfloat162* __restrict__ whl,
    const float* __restrict__ bn, float* __restrict__ out, int W, int logW)
{
    extern __shared__ char smem_raw[];
    const uint32_t sb0 = smem_u32(smem_raw);
    const uint32_t sa = (sb0 + 1023u) & ~1023u;
    char* smem = smem_raw + (sa - sb0);
    const int tid = threadIdx.x, wid = tid >> 5, lane = tid & 31;
    const int HW = W * W;
    const int b = blockIdx.y;
    const int p0 = blockIdx.x * 128;

    float* sSc = (float*)(smem);
    float* sSh = (float*)(smem + 1024);
    if (tid < 256) {
        float sc = bn[tid] * rsqrtf(bn[768 + tid] + 1e-5f);
        sSc[tid] = sc;
        sSh[tid] = bn[256 + tid] - bn[512 + tid] * sc;
    }

    char* Ah = smem + 2048;  char* Al = smem + 18432;
    char* Bh = smem + 34816; char* Bl = smem + 67584;
    const uint32_t aAh = sa + 2048, aAl = sa + 18432;
    const uint32_t aBh = sa + 34816, aBl = sa + 67584;

    const int m0 = (wid & 3) * 32;
    const int n0 = (wid >> 2) * 64;
    const int aRow = lane & 15, aCol = (lane >> 4) * 8;
    const int bRow = (lane & 7) + ((lane >> 4) << 3);
    const int bCol = ((lane >> 3) & 1) * 8;

    float acc[2][8][4];
    #pragma unroll
    for (int i = 0; i < 2; i++)
        #pragma unroll
        for (int j = 0; j < 8; j++)
            #pragma unroll
            for (int q = 0; q < 4; q++) acc[i][j][q] = 0.f;

    for (int ch = 0; ch < 36; ch++) {
        const int kpos = ch >> 2;
        const int ci0 = (ch & 3) * 64;
        const int ky = kpos / 3 - 1, kx = kpos % 3 - 1;
        __syncthreads();
        for (int idx = tid; idx < 128 * 32; idx += 512) {
            int m = idx & 127, c2 = idx >> 7;
            int pix = p0 + m;
            int y = (pix >> logW) + ky, x = (pix & (W - 1)) + kx;
            bool ok = (y >= 0 && y < W && x >= 0 && x < W);
            const float* ip = in + ((size_t)b * FF + ci0 + 2 * c2) * HW + y * W + x;
            float a0 = ok ? ip[0]  : 0.f;
            float a1 = ok ? ip[HW] : 0.f;
            __nv_bfloat16 h0, l0, h1, l1;
            split_bf16(a0, h0, l0); split_bf16(a1, h1, l1);
            uint32_t sw = SWZ(m * 128 + c2 * 4);
            *(__nv_bfloat162*)(Ah + sw) = __halves2bfloat162(h0, h1);
            *(__nv_bfloat162*)(Al + sw) = __halves2bfloat162(l0, l1);
        }
        for (int idx = tid; idx < 256 * 32; idx += 512) {
            int co = idx & 255, c2 = idx >> 8;
            const __nv_bfloat162* wp = whl + ((size_t)kpos * 256 + ci0 + 2 * c2) * 256 + co;
            __nv_bfloat162 wa = wp[0], wb = wp[256];
            uint32_t sw = SWZ(co * 128 + c2 * 4);
            *(__nv_bfloat162*)(Bh + sw) = __halves2bfloat162(wa.x, wb.x);
            *(__nv_bfloat162*)(Bl + sw) = __halves2bfloat162(wa.y, wb.y);
        }
        __syncthreads();
        #pragma unroll
        for (int ks = 0; ks < 4; ks++) {
            const int k0 = ks * 16;
            uint32_t ah[2][4], al[2][4], bh[4][4], bl[4][4];
            #pragma unroll
            for (int mf = 0; mf < 2; mf++) {
                uint32_t off = SWZ((m0 + mf * 16 + aRow) * 128 + (k0 + aCol) * 2);
                ldsm_x4(ah[mf], aAh + off);
                ldsm_x4(al[mf], aAl + off);
            }
            #pragma unroll
            for (int nb = 0; nb < 4; nb++) {
                uint32_t off = SWZ((n0 + nb * 16 + bRow) * 128 + (k0 + bCol) * 2);
                ldsm_x4(bh[nb], aBh + off);
                ldsm_x4(bl[nb], aBl + off);
            }
            #pragma unroll
            for (int mf = 0; mf < 2; mf++)
                #pragma unroll
                for (int nb = 0; nb < 4; nb++)
                    #pragma unroll
                    for (int oc = 0; oc < 2; oc++) {
                        float* d = acc[mf][nb * 2 + oc];
                        mma16816(d, ah[mf], &bh[nb][oc * 2]);
                        mma16816(d, ah[mf], &bl[nb][oc * 2]);
                        mma16816(d, al[mf], &bh[nb][oc * 2]);
                    }
        }
    }

    const int group = lane >> 2, tig = lane & 3;
    #pragma unroll
    for (int mf = 0; mf < 2; mf++)
        #pragma unroll
        for (int nb = 0; nb < 4; nb++)
            #pragma unroll
            for (int oc = 0; oc < 2; oc++) {
                const float* d = acc[mf][nb * 2 + oc];
                int co = n0 + nb * 16 + oc * 8 + tig * 2;
                int m  = m0 + mf * 16 + group;
                float s0 = sSc[co], h0 = sSh[co], s1 = sSc[co+1], h1 = sSh[co+1];
                size_t o0 = ((size_t)b * FF + co) * HW + p0 + m;
                out[o0]           = fmaxf(fmaf(d[0], s0, h0), 0.f);
                out[o0 + HW]      = fmaxf(fmaf(d[1], s1, h1), 0.f);
                out[o0 + 8]       = fmaxf(fmaf(d[2], s0, h0), 0.f);
                out[o0 + HW + 8]  = fmaxf(fmaf(d[3], s1, h1), 0.f);
            }
}

// ---------------- head conv 3x3 (256->1) ----------------
__global__ __launch_bounds__(256) void k_head(const float* __restrict__ wt,
    const float* __restrict__ bias, float* __restrict__ out) {
    __shared__ float sIn[4][18][18];
    __shared__ float sW[4][9];
    const int H = 128, W = 128, HW = H * W;
    const int tx = threadIdx.x, ty = threadIdx.y, tid = ty * 16 + tx;
    const int b = blockIdx.z, x0p = blockIdx.x * 16, y0p = blockIdx.y * 16;
    const float* inb = g_c2 + (size_t)b * FF * HW;
    float acc = 0.f;
    for (int cc = 0; cc < FF; cc += 4) {
        for (int idx = tid; idx < 4 * 324; idx += 256) {
            int ci = idx / 324, rem = idx - ci * 324;
            int iy = rem / 18, ix = rem - iy * 18;
            int yy = y0p + iy - 1, xx = x0p + ix - 1;
            float v = 0.f;
            if (yy >= 0 && yy < H && xx >= 0 && xx < W)
                v = inb[(size_t)(cc + ci) * HW + yy * W + xx];
            sIn[ci][iy][ix] = v;
        }
        if (tid < 36) sW[tid / 9][tid % 9] = wt[(cc + tid / 9) * 9 + tid % 9];
        __syncthreads();
        #pragma unroll
        for (int ci = 0; ci < 4; ci++)
            #pragma unroll
            for (int dy = 0; dy < 3; dy++)
                #pragma unroll
                for (int dx = 0; dx < 3; dx++)
                    acc = fmaf(sIn[ci][ty+dy][tx+dx], sW[ci][dy*3+dx], acc);
        __syncthreads();
    }
    out[(size_t)b * HW + (y0p + ty) * W + (x0p + tx)] = acc + bias[0];
}

// ---------------- launch ----------------
extern "C" void kernel_launch(void* const* d_in, const int* in_sizes, int n_in,
                              void* d_out, int out_size)
{
    const float* f1  = (const float*)d_in[0];
    const float* f2  = (const float*)d_in[1];
    const float* f3  = (const float*)d_in[2];
    const float* f4  = (const float*)d_in[3];
    const float* pw  = (const float*)d_in[4];
    const float* lwv = (const float*)d_in[5];
    const float* dww = (const float*)d_in[6];
    const float* bne = (const float*)d_in[7];
    const float* ow1 = (const float*)d_in[8];
    const float* ob1 = (const float*)d_in[9];
    const float* cw1 = (const float*)d_in[10];
    const float* bn1 = (const float*)d_in[11];
    const float* ow2 = (const float*)d_in[12];
    const float* ob2 = (const float*)d_in[13];
    const float* cw2 = (const float*)d_in[14];
    const float* bn2 = (const float*)d_in[15];
    const float* hw  = (const float*)d_in[16];
    const float* hb  = (const float*)d_in[17];
    float* out = (float*)d_out;

    float *p_x1, *p_off1, *p_up1, *p_c1, *p_off2, *p_up2, *p_c2;
    __nv_bfloat162 *p_w1, *p_w2;
    cudaGetSymbolAddress((void**)&p_x1,  g_x1);
    cudaGetSymbolAddress((void**)&p_off1, g_off1);
    cudaGetSymbolAddress((void**)&p_up1, g_up1);
    cudaGetSymbolAddress((void**)&p_c1,  g_c1);
    cudaGetSymbolAddress((void**)&p_off2, g_off2);
    cudaGetSymbolAddress((void**)&p_up2, g_up2);
    cudaGetSymbolAddress((void**)&p_c2,  g_c2);
    cudaGetSymbolAddress((void**)&p_w1,  g_w1hl);
    cudaGetSymbolAddress((void**)&p_w2,  g_w2hl);

    cudaFuncSetAttribute(k_conv_mma,   cudaFuncAttributeMaxDynamicSharedMemorySize, CM_SMEM);
    cudaFuncSetAttribute(k_fusion_mma, cudaFuncAttributeMaxDynamicSharedMemorySize, FM_SMEM);
    cudaFuncSetAttribute(k_off,        cudaFuncAttributeMaxDynamicSharedMemorySize, KO_SMEM);

    k_prep_w<<<(2*589824)/256, 256>>>(cw1, cw2);
    k_fusion_mma<<<dim3(64, 2), 256, FM_SMEM>>>(f1, f2, f3, f4, pw, lwv);
    k_dw<<<(BB*FF*N0)/256, 256>>>(dww, bne);
    k_off<<<dim3(N0/64, BB), 256, KO_SMEM>>>(p_x1, ow1, ob1, p_off1, N0);
    k_up<<<(BB*FF*4*N0)/256, 256>>>(p_x1, p_off1, p_up1, 32, 32);
    k_conv_mma<<<dim3(4*N0/128, BB), 512, CM_SMEM>>>(p_up1, p_w1, bn1, p_c1, 64, 6);
    k_off<<<dim3(4*N0/64, BB), 256, KO_SMEM>>>(p_c1, ow2, ob2, p_off2, 4*N0);
    k_up<<<(BB*FF*16*N0)/256, 256>>>(p_c1, p_off2, p_up2, 64, 64);
    k_conv_mma<<<dim3(16*N0/128, BB), 512, CM_SMEM>>>(p_up2, p_w2, bn2, p_c2, 128, 7);
    k_head<<<dim3(8, 8, BB), dim3(16, 16)>>>(hw, hb, out);
}

// round 10
// speedup vs baseline: 2.6631x; 1.1119x over previous
#include <cuda_runtime.h>
#include <cuda_bf16.h>
#include <cstdint>
#include <math.h>

#define BB 4
#define CC 768
#define FF 256
#define N0 1024

// ---------------- scratch ----------------
__device__ float g_x0 [BB*FF*N0];
__device__ float g_x1 [BB*FF*N0];
__device__ float g_off1[BB*32*N0];
__device__ float g_off2[BB*32*4*N0];
__device__ float g_c1 [BB*FF*4*N0];
__device__ float g_c2 [BB*FF*16*N0];
// pre-split activations: u32 = bf16x2 {ch 2c2, ch 2c2+1}, planes [b][c2:128][HW]
__device__ uint32_t g_up1H[BB*128*4*N0];
__device__ uint32_t g_up1L[BB*128*4*N0];
__device__ uint32_t g_up2H[BB*128*16*N0];
__device__ uint32_t g_up2L[BB*128*16*N0];
// pre-packed conv weights: [ch36][co256][c2 32] u32
__device__ uint32_t g_w1H[294912], g_w1L[294912];
__device__ uint32_t g_w2H[294912], g_w2L[294912];
// pre-packed fusion weights: [l4][ch12][co256][c2 32]
__device__ uint32_t g_pwH[393216], g_pwL[393216];
__device__ float g_zero4[4] = {0.f, 0.f, 0.f, 0.f};

// ---------------- helpers ----------------
__device__ __forceinline__ uint32_t smem_u32(const void* p) {
    uint32_t a; asm("{ .reg .u64 t; cvta.to.shared.u64 t, %1; cvt.u32.u64 %0, t; }"
                    : "=r"(a) : "l"(p)); return a;
}
#define SWZ(x) ((uint32_t)(x) ^ ((((uint32_t)(x)) >> 3) & 0x70u))

__device__ __forceinline__ void ldsm_x4(uint32_t (&r)[4], uint32_t addr) {
    asm volatile("ldmatrix.sync.aligned.m8n8.x4.shared.b16 {%0,%1,%2,%3}, [%4];"
        : "=r"(r[0]), "=r"(r[1]), "=r"(r[2]), "=r"(r[3]) : "r"(addr));
}
__device__ __forceinline__ void mma16816(float* d, const uint32_t* a, const uint32_t* b) {
    asm volatile("mma.sync.aligned.m16n8k16.row.col.f32.bf16.bf16.f32 "
        "{%0,%1,%2,%3}, {%4,%5,%6,%7}, {%8,%9}, {%0,%1,%2,%3};"
        : "+f"(d[0]), "+f"(d[1]), "+f"(d[2]), "+f"(d[3])
        : "r"(a[0]), "r"(a[1]), "r"(a[2]), "r"(a[3]), "r"(b[0]), "r"(b[1]));
}
__device__ __forceinline__ void split_bf16(float v, __nv_bfloat16& h, __nv_bfloat16& l) {
    h = __float2bfloat16(v);
    l = __float2bfloat16(v - __bfloat162float(h));
}
__device__ __forceinline__ uint32_t pack2(__nv_bfloat16 a, __nv_bfloat16 b) {
    __nv_bfloat162 t = __halves2bfloat162(a, b);
    return *(uint32_t*)&t;
}
#define CP_A4(dst, src)  asm volatile("cp.async.ca.shared.global [%0], [%1], 4;"  :: "r"(dst), "l"(src))
#define CP_A16(dst, src) asm volatile("cp.async.cg.shared.global [%0], [%1], 16;" :: "r"(dst), "l"(src))
#define CP_COMMIT() asm volatile("cp.async.commit_group;" ::: "memory")
#define CP_WAIT0()  asm volatile("cp.async.wait_group 0;" ::: "memory")
#define CP_WAIT1()  asm volatile("cp.async.wait_group 1;" ::: "memory")

// ---------------- weight pre-pack: conv OIHW -> [ch][co][c2] hi/lo u32 ----------------
__global__ __launch_bounds__(256) void k_prep_w(const float* __restrict__ w1,
                                                const float* __restrict__ w2) {
    int idx = blockIdx.x * 256 + threadIdx.x;        // 2*294912
    int which = idx >= 294912;
    int t = which ? idx - 294912 : idx;
    int c2 = t & 31, co = (t >> 5) & 255, ch = t >> 13;
    int kpos = ch >> 2, ci = (ch & 3) * 64 + 2 * c2;
    const float* w = which ? w2 : w1;
    float v0 = w[(co * 256 + ci) * 9 + kpos];
    float v1 = w[(co * 256 + ci + 1) * 9 + kpos];
    __nv_bfloat16 h0, l0, h1, l1;
    split_bf16(v0, h0, l0); split_bf16(v1, h1, l1);
    (which ? g_w2H : g_w1H)[t] = pack2(h0, h1);
    (which ? g_w2L : g_w1L)[t] = pack2(l0, l1);
}

// ---------------- fusion weight pre-pack: proj_w -> [l][ch][co][c2] hi/lo ----------------
__global__ __launch_bounds__(256) void k_prep_pw(const float* __restrict__ pw) {
    int t = blockIdx.x * 256 + threadIdx.x;          // 393216
    int c2 = t & 31, co = (t >> 5) & 255, r = t >> 13;   // r = l*12+ch
    int l = r / 12, ch = r - l * 12;
    int c = ch * 64 + 2 * c2;
    float v0 = pw[((size_t)l * CC + c) * FF + co];
    float v1 = pw[((size_t)l * CC + c + 1) * FF + co];
    __nv_bfloat16 h0, l0, h1, l1;
    split_bf16(v0, h0, l0); split_bf16(v1, h1, l1);
    g_pwH[t] = pack2(h0, h1);
    g_pwL[t] = pack2(l0, l1);
}

// ---------------- fusion GEMM: HMMA bf16 3-term, GELU + weighted layer sum ----------------
#define FM_SMEM (49152 + 1024)
__global__ __launch_bounds__(256) void k_fusion_mma(
    const float* __restrict__ fa, const float* __restrict__ fb,
    const float* __restrict__ fc, const float* __restrict__ fd,
    const float* __restrict__ lwp)
{
    extern __shared__ char smem_raw[];
    const uint32_t sb0 = smem_u32(smem_raw);
    const uint32_t sa = (sb0 + 1023u) & ~1023u;
    char* smem = smem_raw + (sa - sb0);
    const int tid = threadIdx.x, wid = tid >> 5, lane = tid & 31;
    const int mt0 = blockIdx.x * 64;
    const int f0  = blockIdx.y * 128;
    const int m0 = (wid & 1) * 32;
    const int n0 = (wid >> 1) * 32;

    char* Ah = smem;          char* Al = smem + 8192;
    char* Bh = smem + 16384;  char* Bl = smem + 32768;
    const uint32_t aAh = sa, aAl = sa + 8192, aBh = sa + 16384, aBl = sa + 32768;

    float w0 = lwp[0], w1 = lwp[1], w2 = lwp[2], w3 = lwp[3];
    float mx = fmaxf(fmaxf(w0, w1), fmaxf(w2, w3));
    float e0 = expf(w0-mx), e1 = expf(w1-mx), e2 = expf(w2-mx), e3 = expf(w3-mx);
    float inv = 1.0f / (e0+e1+e2+e3);
    float lw[4] = {e0*inv, e1*inv, e2*inv, e3*inv};
    const float* fs[4] = {fa, fb, fc, fd};

    const int aRow = lane & 15, aCol = (lane >> 4) * 8;
    const int bRow = (lane & 7) + ((lane >> 4) << 3);
    const int bCol = ((lane >> 3) & 1) * 8;

    float acc[2][4][4], oacc[2][4][4];
    #pragma unroll
    for (int i = 0; i < 2; i++)
        #pragma unroll
        for (int j = 0; j < 4; j++)
            #pragma unroll
            for (int q = 0; q < 4; q++) { acc[i][j][q] = 0.f; oacc[i][j][q] = 0.f; }

    for (int l = 0; l < 4; l++) {
        const float* fl = fs[l];
        for (int ch = 0; ch < 12; ch++) {
            const int kc0 = ch * 64;
            __syncthreads();
            // A: 64 tokens x 32 c2 (fp32 -> split, each element once)
            for (int idx = tid; idx < 64 * 32; idx += 256) {
                int m = idx & 63, c2 = idx >> 6;
                int pix = mt0 + m, b = pix >> 10, n = pix & 1023;
                const float* ip = fl + ((size_t)b * CC + kc0 + 2 * c2) * N0 + n;
                float a0 = ip[0], a1 = ip[N0];
                __nv_bfloat16 h0, l0, h1, l1;
                split_bf16(a0, h0, l0); split_bf16(a1, h1, l1);
                uint32_t sw = SWZ(m * 128 + c2 * 4);
                *(uint32_t*)(Ah + sw) = pack2(h0, h1);
                *(uint32_t*)(Al + sw) = pack2(l0, l1);
            }
            // B: packed copy from g_pwH/L
            for (int idx = tid; idx < 128 * 32; idx += 256) {
                int co = idx & 127, c2 = idx >> 7;
                size_t src = ((size_t)(l * 12 + ch) * 256 + f0 + co) * 32 + c2;
                uint32_t sw = SWZ(co * 128 + c2 * 4);
                *(uint32_t*)(Bh + sw) = g_pwH[src];
                *(uint32_t*)(Bl + sw) = g_pwL[src];
            }
            __syncthreads();
            #pragma unroll
            for (int ks = 0; ks < 4; ks++) {
                const int k0 = ks * 16;
                uint32_t ah[2][4], al[2][4], bh[2][4], bl[2][4];
                #pragma unroll
                for (int mf = 0; mf < 2; mf++) {
                    uint32_t off = SWZ((m0 + mf * 16 + aRow) * 128 + (k0 + aCol) * 2);
                    ldsm_x4(ah[mf], aAh + off);
                    ldsm_x4(al[mf], aAl + off);
                }
                #pragma unroll
                for (int nb = 0; nb < 2; nb++) {
                    uint32_t off = SWZ((n0 + nb * 16 + bRow) * 128 + (k0 + bCol) * 2);
                    ldsm_x4(bh[nb], aBh + off);
                    ldsm_x4(bl[nb], aBl + off);
                }
                #pragma unroll
                for (int mf = 0; mf < 2; mf++)
                    #pragma unroll
                    for (int nb = 0; nb < 2; nb++)
                        #pragma unroll
                        for (int oc = 0; oc < 2; oc++) {
                            float* d = acc[mf][nb * 2 + oc];
                            mma16816(d, ah[mf], &bh[nb][oc * 2]);
                            mma16816(d, ah[mf], &bl[nb][oc * 2]);
                            mma16816(d, al[mf], &bh[nb][oc * 2]);
                        }
            }
        }
        #pragma unroll
        for (int i = 0; i < 2; i++)
            #pragma unroll
            for (int j = 0; j < 4; j++)
                #pragma unroll
                for (int q = 0; q < 4; q++) {
                    float v = acc[i][j][q];
                    acc[i][j][q] = 0.f;
                    float g = 0.5f * v * (1.0f + erff(v * 0.70710678118654752f));
                    oacc[i][j][q] = fmaf(lw[l], g, oacc[i][j][q]);
                }
    }
    const int group = lane >> 2, tig = lane & 3;
    #pragma unroll
    for (int mf = 0; mf < 2; mf++)
        #pragma unroll
        for (int nb = 0; nb < 2; nb++)
            #pragma unroll
            for (int oc = 0; oc < 2; oc++) {
                const float* d = oacc[mf][nb * 2 + oc];
                int co = f0 + n0 + nb * 16 + oc * 8 + tig * 2;
                int m  = mt0 + m0 + mf * 16 + group;
                int b = m >> 10, n = m & 1023;
                size_t o0 = ((size_t)b * FF + co) * N0 + n;
                g_x0[o0]          = d[0];
                g_x0[o0 + N0]     = d[1];
                g_x0[o0 + 8]      = d[2];
                g_x0[o0 + N0 + 8] = d[3];
            }
}

// ---------------- depthwise + BN + residual ----------------
__global__ __launch_bounds__(256) void k_dw(const float* __restrict__ dww,
                                            const float* __restrict__ bn) {
    int idx = blockIdx.x * 256 + threadIdx.x;
    int w = idx & 31, h = (idx >> 5) & 31, f = (idx >> 10) & 255, b = idx >> 18;
    const float* pl = g_x0 + ((size_t)b*FF + f) * N0;
    float acc = 0.f;
    #pragma unroll
    for (int dy = 0; dy < 3; dy++) {
        int yy = h + dy - 1; if (yy < 0 || yy >= 32) continue;
        #pragma unroll
        for (int dx = 0; dx < 3; dx++) {
            int xx = w + dx - 1; if (xx < 0 || xx >= 32) continue;
            acc = fmaf(pl[yy*32+xx], dww[f*9+dy*3+dx], acc);
        }
    }
    float bnv = (acc - bn[512+f]) * bn[f] * rsqrtf(bn[768+f] + 1e-5f) + bn[256+f];
    g_x1[idx] = fmaxf(bnv + pl[h*32+w], 0.f);
}

// ---------------- offset conv 1x1 (256->32): 64px x 4 k-split groups ----------------
#define KO_SMEM (32768 + 33792)
__global__ __launch_bounds__(256) void k_off(const float* __restrict__ in,
    const float* __restrict__ ow, const float* __restrict__ ob,
    float* __restrict__ out, int HW) {
    extern __shared__ float ko[];
    float (*wT)[32] = (float(*)[32])ko;
    float (*sred)[64][33] = (float(*)[64][33])(ko + 8192);
    const int tid = threadIdx.x;
    for (int idx = tid; idx < 8192; idx += 256)
        wT[idx & 255][idx >> 8] = ow[(idx >> 8) * 256 + (idx & 255)];
    __syncthreads();
    const int px = tid & 63, grp = tid >> 6;
    const int hw = blockIdx.x * 64 + px, b = blockIdx.y;
    float acc[32];
    #pragma unroll
    for (int k = 0; k < 32; k++) acc[k] = 0.f;
    const float* ip = in + ((size_t)b * FF + grp * 64) * HW + hw;
    #pragma unroll 4
    for (int c = 0; c < 64; c++) {
        float v = ip[(size_t)c * HW];
        const float* wr = wT[grp * 64 + c];
        #pragma unroll
        for (int k8 = 0; k8 < 8; k8++) {
            float4 w4 = *(const float4*)&wr[k8 * 4];
            acc[k8*4+0]=fmaf(v,w4.x,acc[k8*4+0]); acc[k8*4+1]=fmaf(v,w4.y,acc[k8*4+1]);
            acc[k8*4+2]=fmaf(v,w4.z,acc[k8*4+2]); acc[k8*4+3]=fmaf(v,w4.w,acc[k8*4+3]);
        }
    }
    #pragma unroll
    for (int k = 0; k < 32; k++) sred[grp][px][k] = acc[k];
    __syncthreads();
    for (int idx = tid; idx < 2048; idx += 256) {
        int k = idx & 31, p = idx >> 5;
        float s = sred[0][p][k] + sred[1][p][k] + sred[2][p][k] + sred[3][p][k] + ob[k];
        out[((size_t)b * 32 + k) * HW + blockIdx.x * 64 + p] = s;
    }
}

// ---------------- DySample bilinear 2x -> packed bf16 hi/lo channel-pair planes ----------------
__global__ __launch_bounds__(256) void k_up(const float* __restrict__ in,
    const float* __restrict__ off, uint32_t* __restrict__ outH,
    uint32_t* __restrict__ outL, int H, int W) {
    int Ho = 2*H, Wo = 2*W;
    int idx = blockIdx.x * 256 + threadIdx.x;      // BB*128*Ho*Wo threads
    int X = idx % Wo; int t = idx / Wo;
    int Y = t % Ho;   t /= Ho;
    int c2 = t & 127, b = t >> 7;
    int cc0 = 2 * c2, g = cc0 >> 6;
    int h = Y >> 1, i = Y & 1, w = X >> 1, j = X & 1;
    int offc = (g << 2) + (i << 1) + j, HW = H * W;
    float ox = off[((size_t)b*32 + offc)*HW + h*W + w] * 0.25f + (j ? 0.25f : -0.25f);
    float oy = off[((size_t)b*32 + 16 + offc)*HW + h*W + w] * 0.25f + (i ? 0.25f : -0.25f);
    float px = fminf(fmaxf((float)w + ox, 0.f), (float)(W-1));
    float py = fminf(fmaxf((float)h + oy, 0.f), (float)(H-1));
    int x0 = (int)floorf(px), y0 = (int)floorf(py);
    float wx = px - x0, wy = py - y0;
    int x1 = min(x0+1, W-1), y1 = min(y0+1, H-1);
    const float* pl = in + ((size_t)b*FF + cc0)*HW;
    float w00 = (1.f-wy)*(1.f-wx), w01 = (1.f-wy)*wx, w10 = wy*(1.f-wx), w11 = wy*wx;
    float va = pl[y0*W+x0]*w00 + pl[y0*W+x1]*w01 + pl[y1*W+x0]*w10 + pl[y1*W+x1]*w11;
    const float* pl1 = pl + HW;
    float vb = pl1[y0*W+x0]*w00 + pl1[y0*W+x1]*w01 + pl1[y1*W+x0]*w10 + pl1[y1*W+x1]*w11;
    __nv_bfloat16 ha, la, hb, lb;
    split_bf16(va, ha, la); split_bf16(vb, hb, lb);
    size_t o = ((size_t)b * 128 + c2) * (Ho * Wo) + Y * Wo + X;
    outH[o] = pack2(ha, hb);
    outL[o] = pack2(la, lb);
}

// ---------------- HMMA implicit-GEMM conv, cp.async double-buffered ----------------
// per stage: Ah@0(16K) Al@16384(16K) Bh@32768(32K) Bl@65536(32K) = 98304
#define STG 98304
#define CM_SMEM (2048 + 2*STG + 1024)
__global__ __launch_bounds__(512) void k_conv_mma(
    const uint32_t* __restrict__ upH, const uint32_t* __restrict__ upL,
    const uint32_t* __restrict__ wH, const uint32_t* __restrict__ wL,
    const float* __restrict__ bn, float* __restrict__ out, int W, int logW)
{
    extern __shared__ char smem_raw[];
    const uint32_t sb0 = smem_u32(smem_raw);
    const uint32_t sa = (sb0 + 1023u) & ~1023u;
    char* smem = smem_raw + (sa - sb0);
    const int tid = threadIdx.x, wid = tid >> 5, lane = tid & 31;
    const int HW = W * W;
    const int b = blockIdx.y;
    const int p0 = blockIdx.x * 128;

    float* sSc = (float*)(smem);
    float* sSh = (float*)(smem + 1024);
    if (tid < 256) {
        float sc = bn[tid] * rsqrtf(bn[768 + tid] + 1e-5f);
        sSc[tid] = sc;
        sSh[tid] = bn[256 + tid] - bn[512 + tid] * sc;
    }

    const uint32_t aStage = sa + 2048;
    const uint64_t zsrc = __cvta_generic_to_global(&g_zero4[0]);

    // fill chunk ch into stage s (cp.async, no commit)
    auto fill = [&](int ch, int s) {
        const int kpos = ch >> 2;
        const int cb2 = (ch & 3) * 32;               // base c2 index (pairs)
        const int ky = kpos / 3 - 1, kx = kpos % 3 - 1;
        const uint32_t stg = aStage + s * STG;
        // A: 128 px x 32 c2, 4B each, zero-buffer for OOB
        #pragma unroll
        for (int r = 0; r < 8; r++) {
            int idx = tid + r * 512;
            int m = idx & 127, c2 = idx >> 7;
            int pix = p0 + m;
            int y = (pix >> logW) + ky, x = (pix & (W - 1)) + kx;
            bool ok = (y >= 0 && y < W && x >= 0 && x < W);
            uint64_t srcH = zsrc, srcL = zsrc;
            if (ok) {
                size_t e = ((size_t)b * 128 + cb2 + c2) * HW + y * W + x;
                srcH = __cvta_generic_to_global(&upH[e]);
                srcL = __cvta_generic_to_global(&upL[e]);
            }
            uint32_t sw = SWZ(m * 128 + c2 * 4);
            CP_A4(stg + sw, srcH);
            CP_A4(stg + 16384 + sw, srcL);
        }
        // B: 256 co x 32 c2, 16B chunks
        #pragma unroll
        for (int r = 0; r < 4; r++) {
            int q = tid + r * 512;                   // 2048 quads
            int co = q >> 3, c2q = q & 7;
            size_t src = ((size_t)ch * 256 + co) * 32 + c2q * 4;
            uint32_t sw = SWZ(co * 128 + c2q * 16);
            CP_A16(stg + 32768 + sw, __cvta_generic_to_global(&wH[src]));
            CP_A16(stg + 65536 + sw, __cvta_generic_to_global(&wL[src]));
        }
    };

    const int m0 = (wid & 3) * 32;
    const int n0 = (wid >> 2) * 64;
    const int aRow = lane & 15, aCol = (lane >> 4) * 8;
    const int bRow = (lane & 7) + ((lane >> 4) << 3);
    const int bCol = ((lane >> 3) & 1) * 8;

    float acc[2][8][4];
    #pragma unroll
    for (int i = 0; i < 2; i++)
        #pragma unroll
        for (int j = 0; j < 8; j++)
            #pragma unroll
            for (int q = 0; q < 4; q++) acc[i][j][q] = 0.f;

    fill(0, 0); CP_COMMIT();

    for (int ch = 0; ch < 36; ch++) {
        if (ch < 35) { fill(ch + 1, (ch + 1) & 1); CP_COMMIT(); CP_WAIT1(); }
        else         { CP_WAIT0(); }
        __syncthreads();
        const uint32_t stg = aStage + (ch & 1) * STG;
        const uint32_t aAh = stg, aAl = stg + 16384, aBh = stg + 32768, aBl = stg + 65536;
        #pragma unroll
        for (int ks = 0; ks < 4; ks++) {
            const int k0 = ks * 16;
            uint32_t ah[2][4], al[2][4], bh[4][4], bl[4][4];
            #pragma unroll
            for (int mf = 0; mf < 2; mf++) {
                uint32_t off = SWZ((m0 + mf * 16 + aRow) * 128 + (k0 + aCol) * 2);
                ldsm_x4(ah[mf], aAh + off);
                ldsm_x4(al[mf], aAl + off);
            }
            #pragma unroll
            for (int nb = 0; nb < 4; nb++) {
                uint32_t off = SWZ((n0 + nb * 16 + bRow) * 128 + (k0 + bCol) * 2);
                ldsm_x4(bh[nb], aBh + off);
                ldsm_x4(bl[nb], aBl + off);
            }
            #pragma unroll
            for (int mf = 0; mf < 2; mf++)
                #pragma unroll
                for (int nb = 0; nb < 4; nb++)
                    #pragma unroll
                    for (int oc = 0; oc < 2; oc++) {
                        float* d = acc[mf][nb * 2 + oc];
                        mma16816(d, ah[mf], &bh[nb][oc * 2]);
                        mma16816(d, ah[mf], &bl[nb][oc * 2]);
                        mma16816(d, al[mf], &bh[nb][oc * 2]);
                    }
        }
        __syncthreads();
    }

    const int group = lane >> 2, tig = lane & 3;
    #pragma unroll
    for (int mf = 0; mf < 2; mf++)
        #pragma unroll
        for (int nb = 0; nb < 4; nb++)
            #pragma unroll
            for (int oc = 0; oc < 2; oc++) {
                const float* d = acc[mf][nb * 2 + oc];
                int co = n0 + nb * 16 + oc * 8 + tig * 2;
                int m  = m0 + mf * 16 + group;
                float s0 = sSc[co], h0 = sSh[co], s1 = sSc[co+1], h1 = sSh[co+1];
                size_t o0 = ((size_t)b * FF + co) * HW + p0 + m;
                out[o0]           = fmaxf(fmaf(d[0], s0, h0), 0.f);
                out[o0 + HW]      = fmaxf(fmaf(d[1], s1, h1), 0.f);
                out[o0 + 8]       = fmaxf(fmaf(d[2], s0, h0), 0.f);
                out[o0 + HW + 8]  = fmaxf(fmaf(d[3], s1, h1), 0.f);
            }
}

// ---------------- head conv 3x3 (256->1) ----------------
__global__ __launch_bounds__(256) void k_head(const float* __restrict__ wt,
    const float* __restrict__ bias, float* __restrict__ out) {
    __shared__ float sIn[4][18][18];
    __shared__ float sW[4][9];
    const int H = 128, W = 128, HW = H * W;
    const int tx = threadIdx.x, ty = threadIdx.y, tid = ty * 16 + tx;
    const int b = blockIdx.z, x0p = blockIdx.x * 16, y0p = blockIdx.y * 16;
    const float* inb = g_c2 + (size_t)b * FF * HW;
    float acc = 0.f;
    for (int cc = 0; cc < FF; cc += 4) {
        for (int idx = tid; idx < 4 * 324; idx += 256) {
            int ci = idx / 324, rem = idx - ci * 324;
            int iy = rem / 18, ix = rem - iy * 18;
            int yy = y0p + iy - 1, xx = x0p + ix - 1;
            float v = 0.f;
            if (yy >= 0 && yy < H && xx >= 0 && xx < W)
                v = inb[(size_t)(cc + ci) * HW + yy * W + xx];
            sIn[ci][iy][ix] = v;
        }
        if (tid < 36) sW[tid / 9][tid % 9] = wt[(cc + tid / 9) * 9 + tid % 9];
        __syncthreads();
        #pragma unroll
        for (int ci = 0; ci < 4; ci++)
            #pragma unroll
            for (int dy = 0; dy < 3; dy++)
                #pragma unroll
                for (int dx = 0; dx < 3; dx++)
                    acc = fmaf(sIn[ci][ty+dy][tx+dx], sW[ci][dy*3+dx], acc);
        __syncthreads();
    }
    out[(size_t)b * HW + (y0p + ty) * W + (x0p + tx)] = acc + bias[0];
}

// ---------------- launch ----------------
extern "C" void kernel_launch(void* const* d_in, const int* in_sizes, int n_in,
                              void* d_out, int out_size)
{
    const float* f1  = (const float*)d_in[0];
    const float* f2  = (const float*)d_in[1];
    const float* f3  = (const float*)d_in[2];
    const float* f4  = (const float*)d_in[3];
    const float* pw  = (const float*)d_in[4];
    const float* lwv = (const float*)d_in[5];
    const float* dww = (const float*)d_in[6];
    const float* bne = (const float*)d_in[7];
    const float* ow1 = (const float*)d_in[8];
    const float* ob1 = (const float*)d_in[9];
    const float* cw1 = (const float*)d_in[10];
    const float* bn1 = (const float*)d_in[11];
    const float* ow2 = (const float*)d_in[12];
    const float* ob2 = (const float*)d_in[13];
    const float* cw2 = (const float*)d_in[14];
    const float* bn2 = (const float*)d_in[15];
    const float* hw  = (const float*)d_in[16];
    const float* hb  = (const float*)d_in[17];
    float* out = (float*)d_out;

    float *p_x1, *p_off1, *p_c1, *p_off2, *p_c2;
    uint32_t *p_u1H, *p_u1L, *p_u2H, *p_u2L, *p_w1H, *p_w1L, *p_w2H, *p_w2L;
    cudaGetSymbolAddress((void**)&p_x1,  g_x1);
    cudaGetSymbolAddress((void**)&p_off1, g_off1);
    cudaGetSymbolAddress((void**)&p_c1,  g_c1);
    cudaGetSymbolAddress((void**)&p_off2, g_off2);
    cudaGetSymbolAddress((void**)&p_c2,  g_c2);
    cudaGetSymbolAddress((void**)&p_u1H, g_up1H);
    cudaGetSymbolAddress((void**)&p_u1L, g_up1L);
    cudaGetSymbolAddress((void**)&p_u2H, g_up2H);
    cudaGetSymbolAddress((void**)&p_u2L, g_up2L);
    cudaGetSymbolAddress((void**)&p_w1H, g_w1H);
    cudaGetSymbolAddress((void**)&p_w1L, g_w1L);
    cudaGetSymbolAddress((void**)&p_w2H, g_w2H);
    cudaGetSymbolAddress((void**)&p_w2L, g_w2L);

    cudaFuncSetAttribute(k_conv_mma,   cudaFuncAttributeMaxDynamicSharedMemorySize, CM_SMEM);
    cudaFuncSetAttribute(k_fusion_mma, cudaFuncAttributeMaxDynamicSharedMemorySize, FM_SMEM);
    cudaFuncSetAttribute(k_off,        cudaFuncAttributeMaxDynamicSharedMemorySize, KO_SMEM);

    k_prep_w<<<(2*294912)/256, 256>>>(cw1, cw2);
    k_prep_pw<<<393216/256, 256>>>(pw);
    k_fusion_mma<<<dim3(64, 2), 256, FM_SMEM>>>(f1, f2, f3, f4, lwv);
    k_dw<<<(BB*FF*N0)/256, 256>>>(dww, bne);
    k_off<<<dim3(N0/64, BB), 256, KO_SMEM>>>(p_x1, ow1, ob1, p_off1, N0);
    k_up<<<(BB*128*4*N0)/256, 256>>>(p_x1, p_off1, p_u1H, p_u1L, 32, 32);
    k_conv_mma<<<dim3(4*N0/128, BB), 512, CM_SMEM>>>(p_u1H, p_u1L, p_w1H, p_w1L, bn1, p_c1, 64, 6);
    k_off<<<dim3(4*N0/64, BB), 256, KO_SMEM>>>(p_c1, ow2, ob2, p_off2, 4*N0);
    k_up<<<(BB*128*16*N0)/256, 256>>>(p_c1, p_off2, p_u2H, p_u2L, 64, 64);
    k_conv_mma<<<dim3(16*N0/128, BB), 512, CM_SMEM>>>(p_u2H, p_u2L, p_w2H, p_w2L, bn2, p_c2, 128, 7);
    k_head<<<dim3(8, 8, BB), dim3(16, 16)>>>(hw, hb, out);
}